// round 5
// baseline (speedup 1.0000x reference)
#include <cuda_runtime.h>
#include <math.h>

// Problem constants
#define B       512
#define D_IN    128
#define D_H     256
#define C_OUT   0      // output channel
#define NS      8      // samples per block in forward kernel

// ---------------- scratch (device globals; no allocation allowed) ------------
__device__ float g_A1[2][B * D_H];
__device__ float g_A2[2][B * D_H];
__device__ float g_D1[2][B * D_H];
__device__ float g_D2[2][B * D_H];
__device__ float g_INV[2][B];
__device__ float g_W2T[D_H * D_H];
__device__ float g_P[6][B * B];     // partial Gram matrices (split-K halves)

// ---------------- W2 transpose (so the backprop matvec is coalesced) ---------
__global__ void k_transpose_w2(const float* __restrict__ W2) {
    int t = blockIdx.x * 256 + threadIdx.x;   // 65536 elems
    int r = t >> 8, c = t & 255;
    g_W2T[c * D_H + r] = W2[t];
}

// ---------------- helpers ----------------------------------------------------
__device__ __forceinline__ float warp_sum(float v) {
#pragma unroll
    for (int o = 16; o; o >>= 1) v += __shfl_xor_sync(0xffffffffu, v, o);
    return v;
}

#define LOAD8(dst, ptr) do {                                              \
    const float4* _p = reinterpret_cast<const float4*>(ptr);              \
    float4 _a = _p[0], _b = _p[1];                                        \
    (dst)[0]=_a.x; (dst)[1]=_a.y; (dst)[2]=_a.z; (dst)[3]=_a.w;           \
    (dst)[4]=_b.x; (dst)[5]=_b.y; (dst)[6]=_b.z; (dst)[7]=_b.w;           \
} while (0)

// ---------------- forward + backward-feature kernel ---------------------------
// grid: (B/NS, 2)  block: 128.  Thread t owns neurons t and t+128 for NS samples.
// NTK factorization: K[i,j] = (<a2_i,a2_j>+1) + (<a1_i,a1_j>+1)<d2_i,d2_j>
//                             + (<x_i,x_j>+1)<d1_i,d1_j>
// with d2 = 1[z2>0].W3[:,C], d1 = 1[z1>0].(W2 d2); ||J_i||^2 = same formula at i=j.
__global__ __launch_bounds__(128)
void k_forward(const float* __restrict__ X1, const float* __restrict__ X2,
               const float* __restrict__ W1, const float* __restrict__ b1,
               const float* __restrict__ W2, const float* __restrict__ b2,
               const float* __restrict__ W3) {
    __shared__ __align__(16) float sx [D_IN * NS];   // [k][s]
    __shared__ __align__(16) float sa1[D_H  * NS];   // [k][s]
    __shared__ __align__(16) float sd2[D_H  * NS];   // [k][s]
    __shared__ float s_wr[5][NS][4];                 // warp partials (4 warps)
    __shared__ float s_sum[5][NS];

    const int t    = threadIdx.x;        // 0..127
    const int j0   = t;                  // neuron 0
    const int j1   = t + 128;            // neuron 1
    const int side = blockIdx.y;
    const int base = blockIdx.x * NS;

    const float* X  = (side == 0) ? X1 : X2;
    float* A1 = g_A1[side]; float* A2 = g_A2[side];
    float* D1 = g_D1[side]; float* D2 = g_D2[side];

    // load x for NS samples, transposed into [k][s]; 1024 elems / 128 thr
#pragma unroll
    for (int p = 0; p < 8; p++) {
        int idx = t + p * 128;
        int s = idx >> 7, k = idx & 127;
        sx[k * NS + s] = X[(base + s) * D_IN + k];
    }
    __syncthreads();

    // ---- layer 1: z1 = x W1 + b1 ----
    float z1[2][NS];
    {
        float b0 = b1[j0], bb1 = b1[j1];
#pragma unroll
        for (int s = 0; s < NS; s++) { z1[0][s] = b0; z1[1][s] = bb1; }
    }
#pragma unroll 8
    for (int k = 0; k < D_IN; k++) {
        float w0 = W1[k * D_H + j0];
        float w1 = W1[k * D_H + j1];
        float xv[NS]; LOAD8(xv, &sx[k * NS]);
#pragma unroll
        for (int s = 0; s < NS; s++) {
            z1[0][s] = fmaf(w0, xv[s], z1[0][s]);
            z1[1][s] = fmaf(w1, xv[s], z1[1][s]);
        }
    }
    float a1r[2][NS];
#pragma unroll
    for (int s = 0; s < NS; s++) {
        a1r[0][s] = fmaxf(z1[0][s], 0.0f);
        a1r[1][s] = fmaxf(z1[1][s], 0.0f);
        sa1[j0 * NS + s] = a1r[0][s];
        sa1[j1 * NS + s] = a1r[1][s];
        A1[(base + s) * D_H + j0] = a1r[0][s];
        A1[(base + s) * D_H + j1] = a1r[1][s];
    }
    __syncthreads();

    // ---- layer 2: z2 = a1 W2 + b2 ----
    float z2[2][NS];
    {
        float b0 = b2[j0], bb1 = b2[j1];
#pragma unroll
        for (int s = 0; s < NS; s++) { z2[0][s] = b0; z2[1][s] = bb1; }
    }
#pragma unroll 8
    for (int k = 0; k < D_H; k++) {
        float w0 = W2[k * D_H + j0];
        float w1 = W2[k * D_H + j1];
        float av[NS]; LOAD8(av, &sa1[k * NS]);
#pragma unroll
        for (int s = 0; s < NS; s++) {
            z2[0][s] = fmaf(w0, av[s], z2[0][s]);
            z2[1][s] = fmaf(w1, av[s], z2[1][s]);
        }
    }
    const float w3c0 = W3[j0 * 10 + C_OUT];
    const float w3c1 = W3[j1 * 10 + C_OUT];
    float a2r[2][NS], d2r[2][NS];
#pragma unroll
    for (int s = 0; s < NS; s++) {
        a2r[0][s] = fmaxf(z2[0][s], 0.0f);
        a2r[1][s] = fmaxf(z2[1][s], 0.0f);
        d2r[0][s] = (z2[0][s] > 0.0f) ? w3c0 : 0.0f;
        d2r[1][s] = (z2[1][s] > 0.0f) ? w3c1 : 0.0f;
        sd2[j0 * NS + s] = d2r[0][s];
        sd2[j1 * NS + s] = d2r[1][s];
        A2[(base + s) * D_H + j0] = a2r[0][s];
        A2[(base + s) * D_H + j1] = a2r[1][s];
        D2[(base + s) * D_H + j0] = d2r[0][s];
        D2[(base + s) * D_H + j1] = d2r[1][s];
    }
    __syncthreads();

    // ---- backprop: d1 = (W2 d2) * 1[z1>0] via W2^T coalesced ----
    float tt[2][NS];
#pragma unroll
    for (int s = 0; s < NS; s++) { tt[0][s] = 0.0f; tt[1][s] = 0.0f; }
#pragma unroll 8
    for (int k = 0; k < D_H; k++) {
        float w0 = g_W2T[k * D_H + j0];
        float w1 = g_W2T[k * D_H + j1];
        float dv[NS]; LOAD8(dv, &sd2[k * NS]);
#pragma unroll
        for (int s = 0; s < NS; s++) {
            tt[0][s] = fmaf(w0, dv[s], tt[0][s]);
            tt[1][s] = fmaf(w1, dv[s], tt[1][s]);
        }
    }
    float d1r[2][NS];
#pragma unroll
    for (int s = 0; s < NS; s++) {
        d1r[0][s] = (z1[0][s] > 0.0f) ? tt[0][s] : 0.0f;
        d1r[1][s] = (z1[1][s] > 0.0f) ? tt[1][s] : 0.0f;
        D1[(base + s) * D_H + j0] = d1r[0][s];
        D1[(base + s) * D_H + j1] = d1r[1][s];
    }

    // ---- per-sample squared norms of {x, a1, a2, d1, d2} ----
    const int lane = t & 31, warp = t >> 5;
#pragma unroll
    for (int s = 0; s < NS; s++) {
        float vx = sx[t * NS + s]; vx *= vx;          // t < 128 == D_IN
        float v1 = a1r[0][s] * a1r[0][s] + a1r[1][s] * a1r[1][s];
        float v2 = a2r[0][s] * a2r[0][s] + a2r[1][s] * a2r[1][s];
        float v3 = d1r[0][s] * d1r[0][s] + d1r[1][s] * d1r[1][s];
        float v4 = d2r[0][s] * d2r[0][s] + d2r[1][s] * d2r[1][s];
        vx = warp_sum(vx); v1 = warp_sum(v1); v2 = warp_sum(v2);
        v3 = warp_sum(v3); v4 = warp_sum(v4);
        if (lane == 0) {
            s_wr[0][s][warp] = vx; s_wr[1][s][warp] = v1; s_wr[2][s][warp] = v2;
            s_wr[3][s][warp] = v3; s_wr[4][s][warp] = v4;
        }
    }
    __syncthreads();
    if (t < 5 * NS) {
        int q = t / NS, s = t % NS;
        float acc = 0.0f;
#pragma unroll
        for (int w = 0; w < 4; w++) acc += s_wr[q][s][w];
        s_sum[q][s] = acc;
    }
    __syncthreads();
    if (t < NS) {
        float sxn = s_sum[0][t], s1 = s_sum[1][t], s2 = s_sum[2][t];
        float sd1 = s_sum[3][t], sd2s = s_sum[4][t];
        float n2 = (s2 + 1.0f) + (s1 + 1.0f) * sd2s + (sxn + 1.0f) * sd1;
        g_INV[side][base + t] = 1.0f / sqrtf(n2);
    }
}

// ---------------- split-K Gram GEMM (64x64 tiles, 4x4 per thread) -------------
// Strided register blocking: thread (ty,tx) owns rows {ty+16r}, cols {tx+16c}.
// b-loads: Bs[(tx+16c)*33+kk] -> bank = (tx+16c+kk)&31 -> 16 distinct banks,
// each address shared by 2 lanes (broadcast). a-loads: 2 addresses/warp.
// Register-prefetch double buffering: next chunk's 16 LDGs issue right after
// the post-store barrier and drain under the 32-step FMA loop.
__device__ __forceinline__ void gram_seg64(const float* __restrict__ Fa,
                                           const float* __restrict__ Fb,
                                           int ld, int kbeg, int klen,
                                           int row0, int col0, int tid,
                                           float acc[4][4],
                                           float* As, float* Bs) {
    const int ty = tid >> 4, tx = tid & 15;
    const int lr = tid >> 5;          // row this thread loads (base), 0..7 step 8
    const int lk = tid & 31;          // k-lane this thread loads

    float ra[8], rb[8];
    // prefetch chunk 0
#pragma unroll
    for (int p = 0; p < 8; p++) {
        int r = lr + p * 8;
        ra[p] = Fa[(row0 + r) * ld + kbeg + lk];
        rb[p] = Fb[(col0 + r) * ld + kbeg + lk];
    }

    for (int k0 = 0; k0 < klen; k0 += 32) {
        __syncthreads();              // previous chunk's compute done
#pragma unroll
        for (int p = 0; p < 8; p++) {
            int r = lr + p * 8;
            As[r * 33 + lk] = ra[p];
            Bs[r * 33 + lk] = rb[p];
        }
        __syncthreads();
        if (k0 + 32 < klen) {         // prefetch next chunk (overlaps compute)
#pragma unroll
            for (int p = 0; p < 8; p++) {
                int r = lr + p * 8;
                ra[p] = Fa[(row0 + r) * ld + kbeg + k0 + 32 + lk];
                rb[p] = Fb[(col0 + r) * ld + kbeg + k0 + 32 + lk];
            }
        }
#pragma unroll
        for (int kk = 0; kk < 32; kk++) {
            float a[4], b[4];
#pragma unroll
            for (int r = 0; r < 4; r++) a[r] = As[(ty + 16 * r) * 33 + kk];
#pragma unroll
            for (int c = 0; c < 4; c++) b[c] = Bs[(tx + 16 * c) * 33 + kk];
#pragma unroll
            for (int r = 0; r < 4; r++)
#pragma unroll
                for (int c = 0; c < 4; c++)
                    acc[r][c] = fmaf(a[r], b[c], acc[r][c]);
        }
    }
}

__global__ __launch_bounds__(256)
void k_gram(const float* __restrict__ X1, const float* __restrict__ X2) {
    __shared__ float As[64 * 33];
    __shared__ float Bs[64 * 33];
    const int tid = threadIdx.x;
    const int row0 = blockIdx.y * 64, col0 = blockIdx.x * 64;
    const int half = blockIdx.z;

    float a0[4][4] = {}, a1[4][4] = {}, a2[4][4] = {};

    if (half == 0) {
        gram_seg64(X1,      X2,      D_IN, 0,   128, row0, col0, tid, a0, As, Bs);
        gram_seg64(g_A1[0], g_A1[1], D_H,  0,   256, row0, col0, tid, a1, As, Bs);
        gram_seg64(g_A2[0], g_A2[1], D_H,  0,   192, row0, col0, tid, a2, As, Bs);
    } else {
        gram_seg64(g_A2[0], g_A2[1], D_H,  192, 64,  row0, col0, tid, a0, As, Bs);
        gram_seg64(g_D1[0], g_D1[1], D_H,  0,   256, row0, col0, tid, a1, As, Bs);
        gram_seg64(g_D2[0], g_D2[1], D_H,  0,   256, row0, col0, tid, a2, As, Bs);
    }

    const int ty = tid >> 4, tx = tid & 15;
    const int pb = half * 3;   // half0 -> P0(Sx),P1(S1),P2(S2a); half1 -> P3(S2b),P4(Sd1),P5(Sd2)
#pragma unroll
    for (int r = 0; r < 4; r++) {
#pragma unroll
        for (int c = 0; c < 4; c++) {
            int i  = row0 + ty + 16 * r;
            int jj = col0 + tx + 16 * c;
            g_P[pb + 0][i * B + jj] = a0[r][c];
            g_P[pb + 1][i * B + jj] = a1[r][c];
            g_P[pb + 2][i * B + jj] = a2[r][c];
        }
    }
}

// ---------------- combine + normalize (vectorized float4) --------------------
__global__ __launch_bounds__(256)
void k_combine(float* __restrict__ out) {
    int q = blockIdx.x * 256 + threadIdx.x;       // quad index, B*B/4 total
    int t = q * 4;
    int i = t >> 9;                                // row (all 4 elems same row)
    int j = t & 511;                               // col of first elem
    float4 sx  = *reinterpret_cast<const float4*>(&g_P[0][t]);
    float4 s1  = *reinterpret_cast<const float4*>(&g_P[1][t]);
    float4 s2a = *reinterpret_cast<const float4*>(&g_P[2][t]);
    float4 s2b = *reinterpret_cast<const float4*>(&g_P[3][t]);
    float4 sd1 = *reinterpret_cast<const float4*>(&g_P[4][t]);
    float4 sd2 = *reinterpret_cast<const float4*>(&g_P[5][t]);
    float inv_i = g_INV[0][i];
    float4 v;
    v.x = ((s2a.x + s2b.x + 1.0f) + (s1.x + 1.0f) * sd2.x + (sx.x + 1.0f) * sd1.x)
          * inv_i * g_INV[1][j + 0];
    v.y = ((s2a.y + s2b.y + 1.0f) + (s1.y + 1.0f) * sd2.y + (sx.y + 1.0f) * sd1.y)
          * inv_i * g_INV[1][j + 1];
    v.z = ((s2a.z + s2b.z + 1.0f) + (s1.z + 1.0f) * sd2.z + (sx.z + 1.0f) * sd1.z)
          * inv_i * g_INV[1][j + 2];
    v.w = ((s2a.w + s2b.w + 1.0f) + (s1.w + 1.0f) * sd2.w + (sx.w + 1.0f) * sd1.w)
          * inv_i * g_INV[1][j + 3];
    *reinterpret_cast<float4*>(&out[t]) = v;
}

// ---------------- launch ------------------------------------------------------
extern "C" void kernel_launch(void* const* d_in, const int* in_sizes, int n_in,
                              void* d_out, int out_size) {
    const float* x1 = (const float*)d_in[0];
    const float* x2 = (const float*)d_in[1];
    const float* W1 = (const float*)d_in[2];
    const float* b1 = (const float*)d_in[3];
    const float* W2 = (const float*)d_in[4];
    const float* b2 = (const float*)d_in[5];
    const float* W3 = (const float*)d_in[6];
    // b3 (d_in[7]) contributes the constant "+1" (one-hot grad) — folded in.
    float* out = (float*)d_out;

    k_transpose_w2<<<D_H * D_H / 256, 256>>>(W2);
    k_forward<<<dim3(B / NS, 2), 128>>>(x1, x2, W1, b1, W2, b2, W3);
    k_gram<<<dim3(B / 64, B / 64, 2), 256>>>(x1, x2);
    k_combine<<<B * B / 1024, 256>>>(out);
}

// round 11
// speedup vs baseline: 1.3697x; 1.3697x over previous
#include <cuda_runtime.h>
#include <math.h>

// Problem constants
#define B       512
#define D_IN    128
#define D_H     256
#define C_OUT   0      // output channel
#define NS      8      // samples per block in forward kernel

// ---------------- scratch (device globals; no allocation allowed) ------------
__device__ float g_A1[2][B * D_H];
__device__ float g_A2[2][B * D_H];
__device__ float g_D1[2][B * D_H];
__device__ float g_D2[2][B * D_H];
__device__ float g_INV[2][B];
__device__ float g_W2T[D_H * D_H];
__device__ float g_P[8][B * B];     // partial Gram planes (split-K quarters)

// ---------------- W2 transpose (so the backprop matvec is coalesced) ---------
__global__ void k_transpose_w2(const float* __restrict__ W2) {
    int t = blockIdx.x * 256 + threadIdx.x;   // 65536 elems
    int r = t >> 8, c = t & 255;
    g_W2T[c * D_H + r] = W2[t];
}

// ---------------- helpers ----------------------------------------------------
__device__ __forceinline__ float warp_sum(float v) {
#pragma unroll
    for (int o = 16; o; o >>= 1) v += __shfl_xor_sync(0xffffffffu, v, o);
    return v;
}

#define LOAD8(dst, ptr) do {                                              \
    const float4* _p = reinterpret_cast<const float4*>(ptr);              \
    float4 _a = _p[0], _b = _p[1];                                        \
    (dst)[0]=_a.x; (dst)[1]=_a.y; (dst)[2]=_a.z; (dst)[3]=_a.w;           \
    (dst)[4]=_b.x; (dst)[5]=_b.y; (dst)[6]=_b.z; (dst)[7]=_b.w;           \
} while (0)

// ---------------- forward + backward-feature kernel ---------------------------
// grid: (B/NS, 2)  block: 256 (8 warps -> 2 warps/SMSP).  Thread t owns neuron t.
// NTK factorization: K[i,j] = (<a2_i,a2_j>+1) + (<a1_i,a1_j>+1)<d2_i,d2_j>
//                             + (<x_i,x_j>+1)<d1_i,d1_j>
// with d2 = 1[z2>0].W3[:,C], d1 = 1[z1>0].(W2 d2); ||J_i||^2 = same formula at i=j.
__global__ __launch_bounds__(256)
void k_forward(const float* __restrict__ X1, const float* __restrict__ X2,
               const float* __restrict__ W1, const float* __restrict__ b1,
               const float* __restrict__ W2, const float* __restrict__ b2,
               const float* __restrict__ W3) {
    __shared__ __align__(16) float sx [D_IN * NS];   // [k][s]
    __shared__ __align__(16) float sa1[D_H  * NS];   // [k][s]
    __shared__ __align__(16) float sd2[D_H  * NS];   // [k][s]
    __shared__ float s_wr[5][NS][8];                 // warp partials (8 warps)
    __shared__ float s_sum[5][NS];

    const int t    = threadIdx.x;        // 0..255 == neuron index
    const int side = blockIdx.y;
    const int base = blockIdx.x * NS;

    const float* X  = (side == 0) ? X1 : X2;
    float* A1 = g_A1[side]; float* A2 = g_A2[side];
    float* D1 = g_D1[side]; float* D2 = g_D2[side];

    // load x for NS samples, transposed into [k][s]; 1024 elems / 256 thr
#pragma unroll
    for (int p = 0; p < 4; p++) {
        int idx = t + p * 256;
        int s = idx >> 7, k = idx & 127;
        sx[k * NS + s] = X[(base + s) * D_IN + k];
    }
    __syncthreads();

    // ---- layer 1: z1 = x W1 + b1 ----
    float z1[NS];
    {
        float bb = b1[t];
#pragma unroll
        for (int s = 0; s < NS; s++) z1[s] = bb;
    }
#pragma unroll 8
    for (int k = 0; k < D_IN; k++) {
        float w = W1[k * D_H + t];
        float xv[NS]; LOAD8(xv, &sx[k * NS]);
#pragma unroll
        for (int s = 0; s < NS; s++) z1[s] = fmaf(w, xv[s], z1[s]);
    }
    float a1r[NS];
#pragma unroll
    for (int s = 0; s < NS; s++) {
        a1r[s] = fmaxf(z1[s], 0.0f);
        sa1[t * NS + s] = a1r[s];
        A1[(base + s) * D_H + t] = a1r[s];
    }
    __syncthreads();

    // ---- layer 2: z2 = a1 W2 + b2 ----
    float z2[NS];
    {
        float bb = b2[t];
#pragma unroll
        for (int s = 0; s < NS; s++) z2[s] = bb;
    }
#pragma unroll 8
    for (int k = 0; k < D_H; k++) {
        float w = W2[k * D_H + t];
        float av[NS]; LOAD8(av, &sa1[k * NS]);
#pragma unroll
        for (int s = 0; s < NS; s++) z2[s] = fmaf(w, av[s], z2[s]);
    }
    const float w3c = W3[t * 10 + C_OUT];
    float a2r[NS], d2r[NS];
#pragma unroll
    for (int s = 0; s < NS; s++) {
        a2r[s] = fmaxf(z2[s], 0.0f);
        d2r[s] = (z2[s] > 0.0f) ? w3c : 0.0f;
        sd2[t * NS + s] = d2r[s];
        A2[(base + s) * D_H + t] = a2r[s];
        D2[(base + s) * D_H + t] = d2r[s];
    }
    __syncthreads();

    // ---- backprop: d1 = (W2 d2) * 1[z1>0] via W2^T coalesced ----
    float tt[NS];
#pragma unroll
    for (int s = 0; s < NS; s++) tt[s] = 0.0f;
#pragma unroll 8
    for (int k = 0; k < D_H; k++) {
        float w = g_W2T[k * D_H + t];
        float dv[NS]; LOAD8(dv, &sd2[k * NS]);
#pragma unroll
        for (int s = 0; s < NS; s++) tt[s] = fmaf(w, dv[s], tt[s]);
    }
    float d1r[NS];
#pragma unroll
    for (int s = 0; s < NS; s++) {
        d1r[s] = (z1[s] > 0.0f) ? tt[s] : 0.0f;
        D1[(base + s) * D_H + t] = d1r[s];
    }

    // ---- per-sample squared norms of {x, a1, a2, d1, d2} ----
    const int lane = t & 31, warp = t >> 5;
#pragma unroll
    for (int s = 0; s < NS; s++) {
        float vx = (t < D_IN) ? sx[t * NS + s] : 0.0f; vx *= vx;
        float v1 = a1r[s] * a1r[s];
        float v2 = a2r[s] * a2r[s];
        float v3 = d1r[s] * d1r[s];
        float v4 = d2r[s] * d2r[s];
        vx = warp_sum(vx); v1 = warp_sum(v1); v2 = warp_sum(v2);
        v3 = warp_sum(v3); v4 = warp_sum(v4);
        if (lane == 0) {
            s_wr[0][s][warp] = vx; s_wr[1][s][warp] = v1; s_wr[2][s][warp] = v2;
            s_wr[3][s][warp] = v3; s_wr[4][s][warp] = v4;
        }
    }
    __syncthreads();
    if (t < 5 * NS) {
        int q = t / NS, s = t % NS;
        float acc = 0.0f;
#pragma unroll
        for (int w = 0; w < 8; w++) acc += s_wr[q][s][w];
        s_sum[q][s] = acc;
    }
    __syncthreads();
    if (t < NS) {
        float sxn = s_sum[0][t], s1 = s_sum[1][t], s2 = s_sum[2][t];
        float sd1 = s_sum[3][t], sd2s = s_sum[4][t];
        float n2 = (s2 + 1.0f) + (s1 + 1.0f) * sd2s + (sxn + 1.0f) * sd1;
        g_INV[side][base + t] = 1.0f / sqrtf(n2);
    }
}

// ---------------- split-K Gram GEMM (64x64 tiles, 4x4 per thread) -------------
// Strided register blocking: thread (ty,tx) owns rows {ty+16r}, cols {tx+16c}.
// b-loads hit 16 distinct banks (stride 33), 2-lane broadcast; a-loads 2 addrs.
// Two latency-hiding layers: register LDG prefetch across chunks, and a
// distance-1 LDS software pipeline inside the kk loop (next kk's fragments load
// under the current kk's 16 FMAs: 32 cyc >= 29-cyc LDS latency).
__device__ __forceinline__ void gram_seg64(const float* __restrict__ Fa,
                                           const float* __restrict__ Fb,
                                           int ld, int kbeg, int klen,
                                           int row0, int col0, int tid,
                                           float acc[4][4],
                                           float* As, float* Bs) {
    const int ty = tid >> 4, tx = tid & 15;
    const int lr = tid >> 5;          // load row base (0..7), rows lr+8p
    const int lk = tid & 31;          // k-lane

    float ra[8], rb[8];
#pragma unroll
    for (int p = 0; p < 8; p++) {
        int r = lr + p * 8;
        ra[p] = Fa[(row0 + r) * ld + kbeg + lk];
        rb[p] = Fb[(col0 + r) * ld + kbeg + lk];
    }

    for (int k0 = 0; k0 < klen; k0 += 32) {
        __syncthreads();              // previous chunk's compute done
#pragma unroll
        for (int p = 0; p < 8; p++) {
            int r = lr + p * 8;
            As[r * 33 + lk] = ra[p];
            Bs[r * 33 + lk] = rb[p];
        }
        __syncthreads();
        if (k0 + 32 < klen) {         // prefetch next chunk (drains under FMAs)
#pragma unroll
            for (int p = 0; p < 8; p++) {
                int r = lr + p * 8;
                ra[p] = Fa[(row0 + r) * ld + kbeg + k0 + 32 + lk];
                rb[p] = Fb[(col0 + r) * ld + kbeg + k0 + 32 + lk];
            }
        }
        // distance-1 LDS pipeline over kk
        float ac[4], bc[4], an[4], bn[4];
#pragma unroll
        for (int r = 0; r < 4; r++) ac[r] = As[(ty + 16 * r) * 33 + 0];
#pragma unroll
        for (int c = 0; c < 4; c++) bc[c] = Bs[(tx + 16 * c) * 33 + 0];
#pragma unroll
        for (int kk = 0; kk < 32; kk++) {
            if (kk < 31) {
#pragma unroll
                for (int r = 0; r < 4; r++) an[r] = As[(ty + 16 * r) * 33 + kk + 1];
#pragma unroll
                for (int c = 0; c < 4; c++) bn[c] = Bs[(tx + 16 * c) * 33 + kk + 1];
            }
#pragma unroll
            for (int r = 0; r < 4; r++)
#pragma unroll
                for (int c = 0; c < 4; c++)
                    acc[r][c] = fmaf(ac[r], bc[c], acc[r][c]);
#pragma unroll
            for (int r = 0; r < 4; r++) { ac[r] = an[r]; bc[r] = bn[r]; }
        }
    }
}

// grid (8, 8, 4): z = K-quarter (288 k each, boundaries on feature edges):
//  q0: x[0:128]   + a1[0:160]  -> planes 0 (Sx),  1 (S1a)
//  q1: a1[160:256]+ a2[0:192]  -> planes 2 (S1b), 3 (S2a)
//  q2: a2[192:256]+ d1[0:224]  -> planes 4 (S2b), 5 (Sd1a)
//  q3: d1[224:256]+ d2[0:256]  -> planes 6 (Sd1b),7 (Sd2)
__global__ __launch_bounds__(256)
void k_gram(const float* __restrict__ X1, const float* __restrict__ X2) {
    __shared__ float As[64 * 33];
    __shared__ float Bs[64 * 33];
    const int tid = threadIdx.x;
    const int row0 = blockIdx.y * 64, col0 = blockIdx.x * 64;
    const int q = blockIdx.z;

    float acc0[4][4] = {}, acc1[4][4] = {};

    const float *a0p, *b0p, *a1p, *b1p;
    int ld0, kb0, kl0, ld1, kb1, kl1, pl0, pl1;
    if (q == 0) {
        a0p = X1;       b0p = X2;       ld0 = D_IN; kb0 = 0;   kl0 = 128;
        a1p = g_A1[0];  b1p = g_A1[1];  ld1 = D_H;  kb1 = 0;   kl1 = 160;
        pl0 = 0; pl1 = 1;
    } else if (q == 1) {
        a0p = g_A1[0];  b0p = g_A1[1];  ld0 = D_H;  kb0 = 160; kl0 = 96;
        a1p = g_A2[0];  b1p = g_A2[1];  ld1 = D_H;  kb1 = 0;   kl1 = 192;
        pl0 = 2; pl1 = 3;
    } else if (q == 2) {
        a0p = g_A2[0];  b0p = g_A2[1];  ld0 = D_H;  kb0 = 192; kl0 = 64;
        a1p = g_D1[0];  b1p = g_D1[1];  ld1 = D_H;  kb1 = 0;   kl1 = 224;
        pl0 = 4; pl1 = 5;
    } else {
        a0p = g_D1[0];  b0p = g_D1[1];  ld0 = D_H;  kb0 = 224; kl0 = 32;
        a1p = g_D2[0];  b1p = g_D2[1];  ld1 = D_H;  kb1 = 0;   kl1 = 256;
        pl0 = 6; pl1 = 7;
    }

    gram_seg64(a0p, b0p, ld0, kb0, kl0, row0, col0, tid, acc0, As, Bs);
    gram_seg64(a1p, b1p, ld1, kb1, kl1, row0, col0, tid, acc1, As, Bs);

    const int ty = tid >> 4, tx = tid & 15;
#pragma unroll
    for (int r = 0; r < 4; r++) {
#pragma unroll
        for (int c = 0; c < 4; c++) {
            int i  = row0 + ty + 16 * r;
            int jj = col0 + tx + 16 * c;
            g_P[pl0][i * B + jj] = acc0[r][c];
            g_P[pl1][i * B + jj] = acc1[r][c];
        }
    }
}

// ---------------- combine + normalize (vectorized float4, 8 planes) ----------
__global__ __launch_bounds__(128)
void k_combine(float* __restrict__ out) {
    int qd = blockIdx.x * 128 + threadIdx.x;      // quad index, B*B/4 total
    int t = qd * 4;
    int i = t >> 9;                                // row (all 4 elems same row)
    int j = t & 511;                               // col of first elem
    float4 sx   = *reinterpret_cast<const float4*>(&g_P[0][t]);
    float4 s1a  = *reinterpret_cast<const float4*>(&g_P[1][t]);
    float4 s1b  = *reinterpret_cast<const float4*>(&g_P[2][t]);
    float4 s2a  = *reinterpret_cast<const float4*>(&g_P[3][t]);
    float4 s2b  = *reinterpret_cast<const float4*>(&g_P[4][t]);
    float4 sd1a = *reinterpret_cast<const float4*>(&g_P[5][t]);
    float4 sd1b = *reinterpret_cast<const float4*>(&g_P[6][t]);
    float4 sd2  = *reinterpret_cast<const float4*>(&g_P[7][t]);
    float inv_i = g_INV[0][i];
    float4 v;
    v.x = ((s2a.x + s2b.x + 1.0f) + (s1a.x + s1b.x + 1.0f) * sd2.x
           + (sx.x + 1.0f) * (sd1a.x + sd1b.x)) * inv_i * g_INV[1][j + 0];
    v.y = ((s2a.y + s2b.y + 1.0f) + (s1a.y + s1b.y + 1.0f) * sd2.y
           + (sx.y + 1.0f) * (sd1a.y + sd1b.y)) * inv_i * g_INV[1][j + 1];
    v.z = ((s2a.z + s2b.z + 1.0f) + (s1a.z + s1b.z + 1.0f) * sd2.z
           + (sx.z + 1.0f) * (sd1a.z + sd1b.z)) * inv_i * g_INV[1][j + 2];
    v.w = ((s2a.w + s2b.w + 1.0f) + (s1a.w + s1b.w + 1.0f) * sd2.w
           + (sx.w + 1.0f) * (sd1a.w + sd1b.w)) * inv_i * g_INV[1][j + 3];
    *reinterpret_cast<float4*>(&out[t]) = v;
}

// ---------------- launch ------------------------------------------------------
extern "C" void kernel_launch(void* const* d_in, const int* in_sizes, int n_in,
                              void* d_out, int out_size) {
    const float* x1 = (const float*)d_in[0];
    const float* x2 = (const float*)d_in[1];
    const float* W1 = (const float*)d_in[2];
    const float* b1 = (const float*)d_in[3];
    const float* W2 = (const float*)d_in[4];
    const float* b2 = (const float*)d_in[5];
    const float* W3 = (const float*)d_in[6];
    // b3 (d_in[7]) contributes the constant "+1" (one-hot grad) — folded in.
    float* out = (float*)d_out;

    k_transpose_w2<<<D_H * D_H / 256, 256>>>(W2);
    k_forward<<<dim3(B / NS, 2), 256>>>(x1, x2, W1, b1, W2, b2, W3);
    k_gram<<<dim3(B / 64, B / 64, 4), 256>>>(x1, x2);
    k_combine<<<B * B / 512, 128>>>(out);
}